// round 6
// baseline (speedup 1.0000x reference)
#include <cuda_runtime.h>

#define EPS 1e-8f
typedef unsigned long long ull;

// Shapes: b=4, m=8, n=128, d=64
__device__ float g_hgw[4 * 8 * 64];     // hg * |w|
__device__ float g_hfw[4 * 128 * 64];   // (hf + b1) * |w|
__device__ float g_htw[4 * 128 * 64];   // ht * |w|
__device__ float g_linG[4 * 8];         // sum_e hg*w
__device__ float g_linF[4 * 128];       // sum_e (hf+b1)*w
__device__ float g_linT[4 * 128];       // sum_e ht*w
__device__ unsigned g_sgnu[64];         // sign mask of W2 per e
__device__ float g_buf[4 * 8 * 128 * 128];
__device__ float g_rowpart[4 * 8 * 128];

__device__ __forceinline__ float warpReduceSum(float v) {
#pragma unroll
    for (int o = 16; o; o >>= 1) v += __shfl_xor_sync(0xffffffffu, v, o);
    return v;
}
__device__ __forceinline__ float warpReduceMax(float v) {
#pragma unroll
    for (int o = 16; o; o >>= 1) v = fmaxf(v, __shfl_xor_sync(0xffffffffu, v, o));
    return v;
}

// acc2 += sign2 .* |gw2 + th2|
__device__ __forceinline__ void mac2(ull& acc, ull gw, ull th, unsigned sl, unsigned sh2) {
    asm("{\n\t"
        ".reg .b64 h2, t2;\n\t"
        ".reg .b32 lo, hi;\n\t"
        "add.rn.f32x2 h2, %1, %2;\n\t"
        "mov.b64 {lo, hi}, h2;\n\t"
        "lop3.b32 lo, lo, 0x7fffffff, %3, 0x6A;\n\t"
        "lop3.b32 hi, hi, 0x7fffffff, %4, 0x6A;\n\t"
        "mov.b64 t2, {lo, hi};\n\t"
        "add.rn.f32x2 %0, %0, t2;\n\t"
        "}"
        : "+l"(acc)
        : "l"(gw), "l"(th), "r"(sl), "r"(sh2));
}

__device__ __forceinline__ unsigned smem_u32(const void* p) {
    unsigned a;
    asm("{ .reg .u64 t; cvta.to.shared.u64 t, %1; cvt.u32.u64 %0, t; }" : "=r"(a) : "l"(p));
    return a;
}
// Fire-and-forget DSMEM store to rank r at the same smem offset.
__device__ __forceinline__ void st_cluster_f32(unsigned addr, int rank, float v) {
    asm volatile(
        "{ .reg .b32 ra; mapa.shared::cluster.u32 ra, %0, %1; st.shared::cluster.f32 [ra], %2; }"
        :: "r"(addr), "r"(rank), "f"(v)
        : "memory");
}
__device__ __forceinline__ void mbar_arrive_rank(unsigned mbar, int rank) {
    asm volatile(
        "{ .reg .b32 ra; mapa.shared::cluster.u32 ra, %0, %1; "
        "mbarrier.arrive.shared::cluster.b64 _, [ra]; }"
        :: "r"(mbar), "r"(rank)
        : "memory");
}
__device__ __forceinline__ void mbar_wait_parity(unsigned mbar, unsigned parity) {
    asm volatile(
        "{\n\t.reg .pred P1;\n\t"
        "WL_%=:\n\t"
        "mbarrier.try_wait.parity.shared::cta.b64 P1, [%0], %1, 0x989680;\n\t"
        "@P1 bra.uni WD_%=;\n\t"
        "bra.uni WL_%=;\n\t"
        "WD_%=:\n\t}"
        :: "r"(mbar), "r"(parity)
        : "memory");
    asm volatile("fence.acq_rel.cluster;" ::: "memory");
}

// ---------------------------------------------------------------------------
// K1 k_proj: grid (264,4), block 64 (same shape as known-good) — inner loop
// restructured for MLP=16 (batch 16 weight loads into regs, then FMA).
// ---------------------------------------------------------------------------
__global__ void k_proj(const float* __restrict__ cities, const float* __restrict__ groups,
                       const float* __restrict__ W1, const float* __restrict__ b1,
                       const float* __restrict__ W2) {
    int b = blockIdx.y;
    int r = blockIdx.x;
    int e = threadIdx.x;
    __shared__ float xv[64];
    __shared__ float sred2[2];

    const float* x;
    float* outw;
    float* lin;
    int woff;
    float badd = 0.f;
    if (r < 8) {
        x = groups + (b * 8 + r) * 64;
        outw = g_hgw + (b * 8 + r) * 64;
        lin = g_linG + b * 8 + r;
        woff = 0;
    } else if (r < 136) {
        int f = r - 8;
        x = cities + (b * 128 + f) * 64;
        outw = g_hfw + (b * 128 + f) * 64;
        lin = g_linF + b * 128 + f;
        woff = 64;
        badd = b1[e];
    } else {
        int t = r - 136;
        x = cities + (b * 128 + t) * 64;
        outw = g_htw + (b * 128 + t) * 64;
        lin = g_linT + b * 128 + t;
        woff = 128;
    }
    xv[e] = x[e];
    if (r == 0 && b == 0) g_sgnu[e] = (W2[e] < 0.f) ? 0x80000000u : 0u;
    __syncthreads();

    const float* Wbase = W1 + woff * 64 + e;
    float acc = 0.f;
#pragma unroll
    for (int kb = 0; kb < 64; kb += 16) {
        float wv[16];
#pragma unroll
        for (int i = 0; i < 16; i++) wv[i] = Wbase[(kb + i) * 64];
#pragma unroll
        for (int i = 0; i < 16; i++) acc += xv[kb + i] * wv[i];
    }
    float h = acc + badd;
    float w = W2[e];
    outw[e] = h * fabsf(w);

    float p = warpReduceSum(h * w);
    if ((e & 31) == 0) sred2[e >> 5] = p;
    __syncthreads();
    if (e == 0) *lin = sred2[0] + sred2[1];
}

// ---------------------------------------------------------------------------
// K2 k_out (verbatim known-good): grid (128,4) x 128.
// ---------------------------------------------------------------------------
__global__ void __launch_bounds__(128) k_out(const float* __restrict__ b2) {
    int b = blockIdx.y, f = blockIdx.x, t = threadIdx.x;
    int w = t >> 5, lane = t & 31;
    __shared__ ull sh_gw[8 * 32];
    __shared__ unsigned sh_sgu[64];
    __shared__ float sh_linG[8];
    __shared__ float s_red[8][4];
    __shared__ float s_bc[8];
    __shared__ float s_m4[4];

    for (int idx = t; idx < 256; idx += 128) {
        int m = idx >> 5, ee2 = idx & 31;
        int e = 2 * ee2;
        float a0 = g_hgw[(b * 8 + m) * 64 + e] + g_hfw[(b * 128 + f) * 64 + e];
        float a1 = g_hgw[(b * 8 + m) * 64 + e + 1] + g_hfw[(b * 128 + f) * 64 + e + 1];
        sh_gw[m * 32 + ee2] = (ull)__float_as_uint(a0) | ((ull)__float_as_uint(a1) << 32);
    }
    if (t < 64) sh_sgu[t] = g_sgnu[t];
    if (t < 8) sh_linG[t] = g_linG[b * 8 + t];
    __syncthreads();

    union {
        float4 f4[16];
        ull u[32];
    } tw;
    const float4* src = (const float4*)(g_htw + (b * 128 + t) * 64);
#pragma unroll
    for (int i = 0; i < 16; i++) tw.f4[i] = src[i];

    ull accs[8];
#pragma unroll
    for (int m = 0; m < 8; m++) accs[m] = 0ull;
#pragma unroll
    for (int ee2 = 0; ee2 < 32; ee2++) {
        unsigned sl = sh_sgu[2 * ee2], sh2 = sh_sgu[2 * ee2 + 1];
        ull th = tw.u[ee2];
#pragma unroll
        for (int m = 0; m < 8; m++) mac2(accs[m], sh_gw[m * 32 + ee2], th, sl, sh2);
    }

    float linFT = g_linF[b * 128 + f] + g_linT[b * 128 + t];
    float b2v = b2[0];
    float vals[8];
#pragma unroll
    for (int m = 0; m < 8; m++) {
        float nl = __uint_as_float((unsigned)(accs[m] & 0xffffffffull)) +
                   __uint_as_float((unsigned)(accs[m] >> 32));
        vals[m] = 0.5f * (sh_linG[m] + linFT + nl) + b2v;
    }

    if (f == 0) {
#pragma unroll
        for (int m = 0; m < 8; m++) {
            float mm = warpReduceMax(vals[m]);
            if (lane == 0) s_red[m][w] = mm;
        }
        __syncthreads();
        if (t < 8) s_bc[t] = fmaxf(fmaxf(s_red[t][0], s_red[t][1]), fmaxf(s_red[t][2], s_red[t][3]));
        __syncthreads();
#pragma unroll
        for (int m = 0; m < 8; m++) {
            float ev = expf(vals[m] - s_bc[m]);
            g_buf[((b * 8 + m) * 128 + 0) * 128 + t] = ev;
            float s = warpReduceSum(fmaxf(ev, EPS));
            if (lane == 0) s_red[m][w] = s;
        }
        __syncthreads();
        if (t < 8)
            g_rowpart[(b * 8 + t) * 128 + 0] = s_red[t][0] + s_red[t][1] + s_red[t][2] + s_red[t][3];
    } else {
        float lm = vals[0];
#pragma unroll
        for (int m = 1; m < 8; m++) lm = fmaxf(lm, vals[m]);
        lm = warpReduceMax(lm);
        if (lane == 0) s_m4[w] = lm;
        __syncthreads();
        float mx = fmaxf(fmaxf(s_m4[0], s_m4[1]), fmaxf(s_m4[2], s_m4[3]));
#pragma unroll
        for (int m = 0; m < 8; m++) {
            float ev = expf(vals[m] - mx);
            g_buf[((b * 8 + m) * 128 + f) * 128 + t] = ev;
            float s = warpReduceSum(fmaxf(ev, EPS));
            if (lane == 0) s_red[m][w] = s;
        }
        __syncthreads();
        if (t < 8)
            g_rowpart[(b * 8 + t) * 128 + f] = s_red[t][0] + s_red[t][1] + s_red[t][2] + s_red[t][3];
    }
}

// ---------------------------------------------------------------------------
// K3 k_soft v4: 10 layers, push-model DSMEM exchange (no cluster.sync in loop).
// Grid 32 = 4 clusters of 8 (cluster = batch). 1024 threads: tid = x*8+jq.
// Thread owns v[m][j] = P[b,m,x, y=rk*16+jq*2+j].
// Per even-den exchange: every CTA PUSHES its local sums into per-rank slots
// of all 8 CTAs (st.shared::cluster), one elected thread fences + remote-
// arrives on all 8 mbarriers; consumers wait parity then sum locally.
// ---------------------------------------------------------------------------
__global__ void __cluster_dims__(8, 1, 1) __launch_bounds__(1024, 1)
k_soft(float* __restrict__ out) {
    const int rk = blockIdx.x & 7;
    const int b = blockIdx.x >> 3;
    const int tid = threadIdx.x;
    const int x = tid >> 3;
    const int jq = tid & 7;
    const int w = tid >> 5;
    const int lane = tid & 31;
    const int yb = rk * 16;
    const bool x0 = (x == 0);
    const bool y0 = (rk == 0 && jq == 0);

    __shared__ ull s_mbar;
    __shared__ float s_xsP[2][8][128];  // pushed per-x sums [buf][src_rank][x]
    __shared__ float s_x0P[2][8][8];    // pushed per-m x==0 sums [buf][src_rank][m]
    __shared__ float s_dinv[128];
    __shared__ float s_d0inv[8];
    __shared__ float s_cdinv[16];
    __shared__ float s_c0inv[8];
    __shared__ float s_wpp[32][16];
    __shared__ float s_y0p[32][8];

    const unsigned mbar = smem_u32(&s_mbar);
    if (tid == 0) {
        asm volatile("mbarrier.init.shared.b64 [%0], %1;" :: "r"(mbar), "r"(8u) : "memory");
    }
    __syncthreads();
    asm volatile("barrier.cluster.arrive.aligned;" ::: "memory");

    // ---- load slab ----
    float v[8][2];
#pragma unroll
    for (int m = 0; m < 8; m++) {
        const float2* p =
            (const float2*)(g_buf + ((size_t)((b * 8 + m) * 128 + x)) * 128 + yb + jq * 2);
        float2 t2 = *p;
        v[m][0] = t2.x;
        v[m][1] = t2.y;
    }

    // ---- layer-0 even dens from g_rowpart ----
    if (tid < 128) {
        float d = 0.f;
#pragma unroll
        for (int m = 0; m < 8; m++) d += g_rowpart[(b * 8 + m) * 128 + tid];
        s_dinv[tid] = 1.0f / d;
    } else if (tid < 136) {
        s_d0inv[tid - 128] = 1.0f / g_rowpart[(b * 8 + (tid - 128)) * 128];
    }
    __syncthreads();
    // all peers' mbarriers initialized before any push below
    asm volatile("barrier.cluster.wait.aligned;" ::: "memory");

#pragma unroll 1
    for (int half = 0; half < 5; half++) {
        // ===== EVEN layer scale + odd-den partials =====
        float sj0 = 0.f, sj1 = 0.f;
        {
            float rinv = s_dinv[x];
#pragma unroll
            for (int m = 0; m < 8; m++) {
                float dm = x0 ? s_d0inv[m] : rinv;
                float a0 = fmaxf(v[m][0], EPS) * dm;
                float a1 = fmaxf(v[m][1], EPS) * dm;
                v[m][0] = a0;
                v[m][1] = a1;
                sj0 += fmaxf(a0, EPS);
                sj1 += fmaxf(a1, EPS);
            }
        }
        sj0 += __shfl_xor_sync(0xffffffffu, sj0, 8);
        sj0 += __shfl_xor_sync(0xffffffffu, sj0, 16);
        sj1 += __shfl_xor_sync(0xffffffffu, sj1, 8);
        sj1 += __shfl_xor_sync(0xffffffffu, sj1, 16);
        if ((lane >> 3) == 0) {
            s_wpp[w][jq * 2 + 0] = sj0;
            s_wpp[w][jq * 2 + 1] = sj1;
        }
        if (rk == 0) {
#pragma unroll
            for (int m = 0; m < 8; m++) {
                float t = fmaxf(v[m][0], EPS);
                t += __shfl_xor_sync(0xffffffffu, t, 8);
                t += __shfl_xor_sync(0xffffffffu, t, 16);
                if (lane == 0) s_y0p[w][m] = t;
            }
        }
        __syncthreads();
        if (tid < 16) {
            float d = 0.f;
#pragma unroll
            for (int ww = 0; ww < 32; ww++) d += s_wpp[ww][tid];
            s_cdinv[tid] = 1.0f / d;
        } else if (tid < 24 && rk == 0) {
            int m = tid - 16;
            float d = 0.f;
#pragma unroll
            for (int ww = 0; ww < 32; ww++) d += s_y0p[ww][m];
            s_c0inv[m] = 1.0f / d;
        }
        __syncthreads();

        // ===== ODD layer scale =====
        float rj0 = s_cdinv[jq * 2], rj1 = s_cdinv[jq * 2 + 1];
        if (half == 4) {
#pragma unroll
            for (int m = 0; m < 8; m++) {
                float2 o;
                o.x = fmaxf(v[m][0], EPS) * (y0 ? s_c0inv[m] : rj0);
                o.y = fmaxf(v[m][1], EPS) * rj1;
                *(float2*)(out + ((size_t)((b * 8 + m) * 128 + x)) * 128 + yb + jq * 2) = o;
            }
            break;
        }
        float rp = 0.f;
#pragma unroll
        for (int m = 0; m < 8; m++) {
            float a0 = fmaxf(v[m][0], EPS) * (y0 ? s_c0inv[m] : rj0);
            float a1 = fmaxf(v[m][1], EPS) * rj1;
            v[m][0] = a0;
            v[m][1] = a1;
            rp += fmaxf(a0, EPS) + fmaxf(a1, EPS);
        }
        rp += __shfl_xor_sync(0xffffffffu, rp, 1);
        rp += __shfl_xor_sync(0xffffffffu, rp, 2);
        rp += __shfl_xor_sync(0xffffffffu, rp, 4);
        float myx0 = 0.f;
        if (w == 0) {
#pragma unroll
            for (int m = 0; m < 8; m++) {
                float t = fmaxf(v[m][0], EPS) + fmaxf(v[m][1], EPS);
                t += __shfl_xor_sync(0xffffffffu, t, 1);
                t += __shfl_xor_sync(0xffffffffu, t, 2);
                t += __shfl_xor_sync(0xffffffffu, t, 4);
                if (lane == m) myx0 = t;
            }
        }

        // ---- PUSH local sums into all 8 CTAs' slots, then arrive ----
        const int p = half & 1;
        if ((lane & 7) == 0) {
            unsigned a = smem_u32(&s_xsP[p][rk][x]);
#pragma unroll
            for (int r = 0; r < 8; r++) st_cluster_f32(a, r, rp);
        }
        if (w == 0 && lane < 8) {
            unsigned a = smem_u32(&s_x0P[p][rk][lane]);
#pragma unroll
            for (int r = 0; r < 8; r++) st_cluster_f32(a, r, myx0);
        }
        __syncthreads();
        if (tid == 0) {
            asm volatile("fence.acq_rel.cluster;" ::: "memory");
#pragma unroll
            for (int r = 0; r < 8; r++) mbar_arrive_rank(mbar, r);
        }

        // ---- consume: wait for 8 arrivals, sum slots locally ----
        if (tid < 136) {
            mbar_wait_parity(mbar, (unsigned)(half & 1));
            if (tid < 128) {
                float d = 0.f;
#pragma unroll
                for (int r = 0; r < 8; r++) d += s_xsP[p][r][tid];
                s_dinv[tid] = 1.0f / d;
            } else {
                int m = tid - 128;
                float d = 0.f;
#pragma unroll
                for (int r = 0; r < 8; r++) d += s_x0P[p][r][m];
                s_d0inv[m] = 1.0f / d;
            }
        }
        __syncthreads();
    }
}

// ---------------------------------------------------------------------------
// Launch: 3 kernels.
// ---------------------------------------------------------------------------
extern "C" void kernel_launch(void* const* d_in, const int* in_sizes, int n_in,
                              void* d_out, int out_size) {
    const float* cities = (const float*)d_in[0];
    const float* groups = (const float*)d_in[1];
    const float* W1 = (const float*)d_in[2];
    const float* b1 = (const float*)d_in[3];
    const float* W2 = (const float*)d_in[4];
    const float* b2 = (const float*)d_in[5];
    float* out = (float*)d_out;

    k_proj<<<dim3(264, 4), 64>>>(cities, groups, W1, b1, W2);
    k_out<<<dim3(128, 4), 128>>>(b2);
    k_soft<<<32, 1024>>>(out);
}

// round 7
// speedup vs baseline: 1.0437x; 1.0437x over previous
#include <cuda_runtime.h>
#include <cooperative_groups.h>

namespace cg = cooperative_groups;

#define EPS 1e-8f
typedef unsigned long long ull;

// Shapes: b=4, m=8, n=128, d=64
__device__ float g_hgw[4 * 8 * 64];     // hg * |w|
__device__ float g_hfw[4 * 128 * 64];   // (hf + b1) * |w|
__device__ float g_htw[4 * 128 * 64];   // ht * |w|
__device__ float g_linG[4 * 8];         // sum_e hg*w
__device__ float g_linF[4 * 128];       // sum_e (hf+b1)*w
__device__ float g_linT[4 * 128];       // sum_e ht*w
__device__ float g_buf[4 * 8 * 128 * 128];
__device__ float g_rowpart[4 * 8 * 128];

__device__ __forceinline__ void pdl_trigger() {
    asm volatile("griddepcontrol.launch_dependents;" ::: "memory");
}
__device__ __forceinline__ void pdl_wait() {
    asm volatile("griddepcontrol.wait;" ::: "memory");
}

__device__ __forceinline__ float warpReduceSum(float v) {
#pragma unroll
    for (int o = 16; o; o >>= 1) v += __shfl_xor_sync(0xffffffffu, v, o);
    return v;
}
__device__ __forceinline__ float warpReduceMax(float v) {
#pragma unroll
    for (int o = 16; o; o >>= 1) v = fmaxf(v, __shfl_xor_sync(0xffffffffu, v, o));
    return v;
}

// acc2 += sign2 .* |gw2 + th2|
__device__ __forceinline__ void mac2(ull& acc, ull gw, ull th, unsigned sl, unsigned sh2) {
    asm("{\n\t"
        ".reg .b64 h2, t2;\n\t"
        ".reg .b32 lo, hi;\n\t"
        "add.rn.f32x2 h2, %1, %2;\n\t"
        "mov.b64 {lo, hi}, h2;\n\t"
        "lop3.b32 lo, lo, 0x7fffffff, %3, 0x6A;\n\t"
        "lop3.b32 hi, hi, 0x7fffffff, %4, 0x6A;\n\t"
        "mov.b64 t2, {lo, hi};\n\t"
        "add.rn.f32x2 %0, %0, t2;\n\t"
        "}"
        : "+l"(acc)
        : "l"(gw), "l"(th), "r"(sl), "r"(sh2));
}

// ---------------------------------------------------------------------------
// K1 k_proj: grid (264,4), block 64 — MLP-16 inner loop (R6, 7.0us).
// ---------------------------------------------------------------------------
__global__ void k_proj(const float* __restrict__ cities, const float* __restrict__ groups,
                       const float* __restrict__ W1, const float* __restrict__ b1,
                       const float* __restrict__ W2) {
    pdl_trigger();
    int b = blockIdx.y;
    int r = blockIdx.x;
    int e = threadIdx.x;
    __shared__ float xv[64];
    __shared__ float sred2[2];

    const float* x;
    float* outw;
    float* lin;
    int woff;
    float badd = 0.f;
    if (r < 8) {
        x = groups + (b * 8 + r) * 64;
        outw = g_hgw + (b * 8 + r) * 64;
        lin = g_linG + b * 8 + r;
        woff = 0;
    } else if (r < 136) {
        int f = r - 8;
        x = cities + (b * 128 + f) * 64;
        outw = g_hfw + (b * 128 + f) * 64;
        lin = g_linF + b * 128 + f;
        woff = 64;
        badd = b1[e];
    } else {
        int t = r - 136;
        x = cities + (b * 128 + t) * 64;
        outw = g_htw + (b * 128 + t) * 64;
        lin = g_linT + b * 128 + t;
        woff = 128;
    }
    xv[e] = x[e];
    __syncthreads();

    const float* Wbase = W1 + woff * 64 + e;
    float acc = 0.f;
#pragma unroll
    for (int kb = 0; kb < 64; kb += 16) {
        float wv[16];
#pragma unroll
        for (int i = 0; i < 16; i++) wv[i] = Wbase[(kb + i) * 64];
#pragma unroll
        for (int i = 0; i < 16; i++) acc += xv[kb + i] * wv[i];
    }
    float h = acc + badd;
    float w = W2[e];
    outw[e] = h * fabsf(w);

    float p = warpReduceSum(h * w);
    if ((e & 31) == 0) sred2[e >> 5] = p;
    __syncthreads();
    if (e == 0) *lin = sred2[0] + sred2[1];
}

// ---------------------------------------------------------------------------
// K2 k_out: grid (128,4) x 128. PDL: trigger at entry; preamble derives sign
// masks from W2 (input) + loads b2, then waits on k_proj before touching g_*.
// ---------------------------------------------------------------------------
__global__ void __launch_bounds__(128) k_out(const float* __restrict__ W2,
                                             const float* __restrict__ b2) {
    pdl_trigger();
    int b = blockIdx.y, f = blockIdx.x, t = threadIdx.x;
    int w = t >> 5, lane = t & 31;
    __shared__ ull sh_gw[8 * 32];
    __shared__ unsigned sh_sgu[64];
    __shared__ float sh_linG[8];
    __shared__ float s_red[8][4];
    __shared__ float s_bc[8];
    __shared__ float s_m4[4];

    // producer-independent preamble
    if (t < 64) sh_sgu[t] = __float_as_uint(W2[t]) & 0x80000000u;
    float b2v = b2[0];

    pdl_wait();  // k_proj results visible from here

    for (int idx = t; idx < 256; idx += 128) {
        int m = idx >> 5, ee2 = idx & 31;
        int e = 2 * ee2;
        float a0 = g_hgw[(b * 8 + m) * 64 + e] + g_hfw[(b * 128 + f) * 64 + e];
        float a1 = g_hgw[(b * 8 + m) * 64 + e + 1] + g_hfw[(b * 128 + f) * 64 + e + 1];
        sh_gw[m * 32 + ee2] = (ull)__float_as_uint(a0) | ((ull)__float_as_uint(a1) << 32);
    }
    if (t < 8) sh_linG[t] = g_linG[b * 8 + t];
    __syncthreads();

    union {
        float4 f4[16];
        ull u[32];
    } tw;
    const float4* src = (const float4*)(g_htw + (b * 128 + t) * 64);
#pragma unroll
    for (int i = 0; i < 16; i++) tw.f4[i] = src[i];

    ull accs[8];
#pragma unroll
    for (int m = 0; m < 8; m++) accs[m] = 0ull;
#pragma unroll
    for (int ee2 = 0; ee2 < 32; ee2++) {
        unsigned sl = sh_sgu[2 * ee2], sh2 = sh_sgu[2 * ee2 + 1];
        ull th = tw.u[ee2];
#pragma unroll
        for (int m = 0; m < 8; m++) mac2(accs[m], sh_gw[m * 32 + ee2], th, sl, sh2);
    }

    float linFT = g_linF[b * 128 + f] + g_linT[b * 128 + t];
    float vals[8];
#pragma unroll
    for (int m = 0; m < 8; m++) {
        float nl = __uint_as_float((unsigned)(accs[m] & 0xffffffffull)) +
                   __uint_as_float((unsigned)(accs[m] >> 32));
        vals[m] = 0.5f * (sh_linG[m] + linFT + nl) + b2v;
    }

    if (f == 0) {
#pragma unroll
        for (int m = 0; m < 8; m++) {
            float mm = warpReduceMax(vals[m]);
            if (lane == 0) s_red[m][w] = mm;
        }
        __syncthreads();
        if (t < 8) s_bc[t] = fmaxf(fmaxf(s_red[t][0], s_red[t][1]), fmaxf(s_red[t][2], s_red[t][3]));
        __syncthreads();
#pragma unroll
        for (int m = 0; m < 8; m++) {
            float ev = expf(vals[m] - s_bc[m]);
            g_buf[((b * 8 + m) * 128 + 0) * 128 + t] = ev;
            float s = warpReduceSum(fmaxf(ev, EPS));
            if (lane == 0) s_red[m][w] = s;
        }
        __syncthreads();
        if (t < 8)
            g_rowpart[(b * 8 + t) * 128 + 0] = s_red[t][0] + s_red[t][1] + s_red[t][2] + s_red[t][3];
    } else {
        float lm = vals[0];
#pragma unroll
        for (int m = 1; m < 8; m++) lm = fmaxf(lm, vals[m]);
        lm = warpReduceMax(lm);
        if (lane == 0) s_m4[w] = lm;
        __syncthreads();
        float mx = fmaxf(fmaxf(s_m4[0], s_m4[1]), fmaxf(s_m4[2], s_m4[3]));
#pragma unroll
        for (int m = 0; m < 8; m++) {
            float ev = expf(vals[m] - mx);
            g_buf[((b * 8 + m) * 128 + f) * 128 + t] = ev;
            float s = warpReduceSum(fmaxf(ev, EPS));
            if (lane == 0) s_red[m][w] = s;
        }
        __syncthreads();
        if (t < 8)
            g_rowpart[(b * 8 + t) * 128 + f] = s_red[t][0] + s_red[t][1] + s_red[t][2] + s_red[t][3];
    }
}

// ---------------------------------------------------------------------------
// K3 k_soft v3 (R5 known-good, cluster.sync) + PDL wait before g_* reads.
// Grid 32 = 4 clusters of 8. 1024 threads: tid = x*8+jq.
// ---------------------------------------------------------------------------
__global__ void __cluster_dims__(8, 1, 1) __launch_bounds__(1024, 1)
k_soft(float* __restrict__ out) {
    cg::cluster_group cl = cg::this_cluster();
    const int rk = (int)cl.block_rank();
    const int b = blockIdx.x >> 3;
    const int tid = threadIdx.x;
    const int x = tid >> 3;
    const int jq = tid & 7;
    const int w = tid >> 5;
    const int lane = tid & 31;
    const int yb = rk * 16;
    const bool x0 = (x == 0);
    const bool y0 = (rk == 0 && jq == 0);

    __shared__ float s_dinv[128];
    __shared__ float s_d0inv[8];
    __shared__ float s_cdinv[16];
    __shared__ float s_c0inv[8];
    __shared__ float s_wpp[32][16];
    __shared__ float s_y0p[32][8];
    __shared__ float s_xs[2][128];
    __shared__ float s_x0[2][8];

    pdl_wait();  // k_out results visible from here

    float v[8][2];
#pragma unroll
    for (int m = 0; m < 8; m++) {
        const float2* p =
            (const float2*)(g_buf + ((size_t)((b * 8 + m) * 128 + x)) * 128 + yb + jq * 2);
        float2 t2 = *p;
        v[m][0] = t2.x;
        v[m][1] = t2.y;
    }

    if (tid < 128) {
        float d = 0.f;
#pragma unroll
        for (int m = 0; m < 8; m++) d += g_rowpart[(b * 8 + m) * 128 + tid];
        s_dinv[tid] = 1.0f / d;
    } else if (tid < 136) {
        s_d0inv[tid - 128] = 1.0f / g_rowpart[(b * 8 + (tid - 128)) * 128];
    }
    __syncthreads();

#pragma unroll 1
    for (int half = 0; half < 5; half++) {
        float sj0 = 0.f, sj1 = 0.f;
        {
            float rinv = s_dinv[x];
#pragma unroll
            for (int m = 0; m < 8; m++) {
                float dm = x0 ? s_d0inv[m] : rinv;
                float a0 = fmaxf(v[m][0], EPS) * dm;
                float a1 = fmaxf(v[m][1], EPS) * dm;
                v[m][0] = a0;
                v[m][1] = a1;
                sj0 += fmaxf(a0, EPS);
                sj1 += fmaxf(a1, EPS);
            }
        }
        sj0 += __shfl_xor_sync(0xffffffffu, sj0, 8);
        sj0 += __shfl_xor_sync(0xffffffffu, sj0, 16);
        sj1 += __shfl_xor_sync(0xffffffffu, sj1, 8);
        sj1 += __shfl_xor_sync(0xffffffffu, sj1, 16);
        if ((lane >> 3) == 0) {
            s_wpp[w][jq * 2 + 0] = sj0;
            s_wpp[w][jq * 2 + 1] = sj1;
        }
        if (rk == 0) {
#pragma unroll
            for (int m = 0; m < 8; m++) {
                float t = fmaxf(v[m][0], EPS);
                t += __shfl_xor_sync(0xffffffffu, t, 8);
                t += __shfl_xor_sync(0xffffffffu, t, 16);
                if (lane == 0) s_y0p[w][m] = t;
            }
        }
        __syncthreads();
        if (tid < 16) {
            float d = 0.f;
#pragma unroll
            for (int ww = 0; ww < 32; ww++) d += s_wpp[ww][tid];
            s_cdinv[tid] = 1.0f / d;
        } else if (tid < 24 && rk == 0) {
            int m = tid - 16;
            float d = 0.f;
#pragma unroll
            for (int ww = 0; ww < 32; ww++) d += s_y0p[ww][m];
            s_c0inv[m] = 1.0f / d;
        }
        __syncthreads();

        float rj0 = s_cdinv[jq * 2], rj1 = s_cdinv[jq * 2 + 1];
        if (half == 4) {
#pragma unroll
            for (int m = 0; m < 8; m++) {
                float2 o;
                o.x = fmaxf(v[m][0], EPS) * (y0 ? s_c0inv[m] : rj0);
                o.y = fmaxf(v[m][1], EPS) * rj1;
                *(float2*)(out + ((size_t)((b * 8 + m) * 128 + x)) * 128 + yb + jq * 2) = o;
            }
            break;
        }
        float rp = 0.f;
#pragma unroll
        for (int m = 0; m < 8; m++) {
            float a0 = fmaxf(v[m][0], EPS) * (y0 ? s_c0inv[m] : rj0);
            float a1 = fmaxf(v[m][1], EPS) * rj1;
            v[m][0] = a0;
            v[m][1] = a1;
            rp += fmaxf(a0, EPS) + fmaxf(a1, EPS);
        }
        rp += __shfl_xor_sync(0xffffffffu, rp, 1);
        rp += __shfl_xor_sync(0xffffffffu, rp, 2);
        rp += __shfl_xor_sync(0xffffffffu, rp, 4);
        int p = half & 1;
        if ((lane & 7) == 0) s_xs[p][x] = rp;
        if (w == 0) {
#pragma unroll
            for (int m = 0; m < 8; m++) {
                float t = fmaxf(v[m][0], EPS) + fmaxf(v[m][1], EPS);
                t += __shfl_xor_sync(0xffffffffu, t, 1);
                t += __shfl_xor_sync(0xffffffffu, t, 2);
                t += __shfl_xor_sync(0xffffffffu, t, 4);
                if (lane == 0) s_x0[p][m] = t;
            }
        }
        cl.sync();

        if (tid < 128) {
            float d = 0.f;
#pragma unroll
            for (int r = 0; r < 8; r++) {
                const float* pp = cl.map_shared_rank((const float*)&s_xs[p][0], r);
                d += pp[tid];
            }
            s_dinv[tid] = 1.0f / d;
        } else if (tid < 136) {
            int m = tid - 128;
            float d = 0.f;
#pragma unroll
            for (int r = 0; r < 8; r++) {
                const float* pp = cl.map_shared_rank((const float*)&s_x0[p][0], r);
                d += pp[m];
            }
            s_d0inv[m] = 1.0f / d;
        }
        __syncthreads();
    }

    cl.sync();
}

// ---------------------------------------------------------------------------
// Launch: 3 kernels, PDL-chained (programmatic stream serialization).
// ---------------------------------------------------------------------------
extern "C" void kernel_launch(void* const* d_in, const int* in_sizes, int n_in,
                              void* d_out, int out_size) {
    const float* cities = (const float*)d_in[0];
    const float* groups = (const float*)d_in[1];
    const float* W1 = (const float*)d_in[2];
    const float* b1 = (const float*)d_in[3];
    const float* W2 = (const float*)d_in[4];
    const float* b2 = (const float*)d_in[5];
    float* out = (float*)d_out;

    // K1: normal launch
    k_proj<<<dim3(264, 4), 64>>>(cities, groups, W1, b1, W2);

    // K2: PDL-dependent on K1
    {
        cudaLaunchConfig_t cfg = {};
        cfg.gridDim = dim3(128, 4);
        cfg.blockDim = dim3(128);
        cfg.stream = 0;
        cudaLaunchAttribute at[1];
        at[0].id = cudaLaunchAttributeProgrammaticStreamSerialization;
        at[0].val.programmaticStreamSerializationAllowed = 1;
        cfg.attrs = at;
        cfg.numAttrs = 1;
        cudaLaunchKernelEx(&cfg, k_out, W2, b2);
    }

    // K3: PDL-dependent on K2 (cluster dims come from __cluster_dims__)
    {
        cudaLaunchConfig_t cfg = {};
        cfg.gridDim = dim3(32);
        cfg.blockDim = dim3(1024);
        cfg.stream = 0;
        cudaLaunchAttribute at[1];
        at[0].id = cudaLaunchAttributeProgrammaticStreamSerialization;
        at[0].val.programmaticStreamSerializationAllowed = 1;
        cfg.attrs = at;
        cfg.numAttrs = 1;
        cudaLaunchKernelEx(&cfg, k_soft, out);
    }
}

// round 8
// speedup vs baseline: 1.0676x; 1.0229x over previous
#include <cuda_runtime.h>
#include <cooperative_groups.h>

namespace cg = cooperative_groups;

#define EPS 1e-8f
typedef unsigned long long ull;

// Shapes: b=4, m=8, n=128, d=64
__device__ float g_hgw[4 * 8 * 64];     // hg * |w|
__device__ float g_hfw[4 * 128 * 64];   // (hf + b1) * |w|
__device__ float g_htw[4 * 128 * 64];   // ht * |w|
__device__ float g_linG[4 * 8];         // sum_e hg*w
__device__ float g_linF[4 * 128];       // sum_e (hf+b1)*w
__device__ float g_linT[4 * 128];       // sum_e ht*w
__device__ float g_buf[4 * 8 * 128 * 128];
__device__ float g_rowpart[4 * 8 * 128];

__device__ __forceinline__ void pdl_trigger() {
    asm volatile("griddepcontrol.launch_dependents;" ::: "memory");
}
__device__ __forceinline__ void pdl_wait() {
    asm volatile("griddepcontrol.wait;" ::: "memory");
}

__device__ __forceinline__ float warpReduceSum(float v) {
#pragma unroll
    for (int o = 16; o; o >>= 1) v += __shfl_xor_sync(0xffffffffu, v, o);
    return v;
}
__device__ __forceinline__ float warpReduceMax(float v) {
#pragma unroll
    for (int o = 16; o; o >>= 1) v = fmaxf(v, __shfl_xor_sync(0xffffffffu, v, o));
    return v;
}

// ---- packed f32x2 helpers ----
__device__ __forceinline__ ull pk2(float x, float y) {
    ull r;
    asm("mov.b64 %0, {%1, %2};" : "=l"(r) : "f"(x), "f"(y));
    return r;
}
__device__ __forceinline__ float lo2(ull a) {
    float x;
    asm("{ .reg .b32 hi; mov.b64 {%0, hi}, %1; }" : "=f"(x) : "l"(a));
    return x;
}
__device__ __forceinline__ float hi2(ull a) {
    float x;
    asm("{ .reg .b32 lo; mov.b64 {lo, %0}, %1; }" : "=f"(x) : "l"(a));
    return x;
}
__device__ __forceinline__ ull mul2(ull a, ull b) {
    ull d;
    asm("mul.rn.f32x2 %0, %1, %2;" : "=l"(d) : "l"(a), "l"(b));
    return d;
}
__device__ __forceinline__ ull add2(ull a, ull b) {
    ull d;
    asm("add.rn.f32x2 %0, %1, %2;" : "=l"(d) : "l"(a), "l"(b));
    return d;
}

// acc2 += sign2 .* |gw2 + th2|
__device__ __forceinline__ void mac2(ull& acc, ull gw, ull th, unsigned sl, unsigned sh2) {
    asm("{\n\t"
        ".reg .b64 h2, t2;\n\t"
        ".reg .b32 lo, hi;\n\t"
        "add.rn.f32x2 h2, %1, %2;\n\t"
        "mov.b64 {lo, hi}, h2;\n\t"
        "lop3.b32 lo, lo, 0x7fffffff, %3, 0x6A;\n\t"
        "lop3.b32 hi, hi, 0x7fffffff, %4, 0x6A;\n\t"
        "mov.b64 t2, {lo, hi};\n\t"
        "add.rn.f32x2 %0, %0, t2;\n\t"
        "}"
        : "+l"(acc)
        : "l"(gw), "l"(th), "r"(sl), "r"(sh2));
}

// ---------------------------------------------------------------------------
// K1 k_proj: grid (264,4), block 64 — MLP-16 inner loop (R6/R7 verbatim).
// ---------------------------------------------------------------------------
__global__ void k_proj(const float* __restrict__ cities, const float* __restrict__ groups,
                       const float* __restrict__ W1, const float* __restrict__ b1,
                       const float* __restrict__ W2) {
    pdl_trigger();
    int b = blockIdx.y;
    int r = blockIdx.x;
    int e = threadIdx.x;
    __shared__ float xv[64];
    __shared__ float sred2[2];

    const float* x;
    float* outw;
    float* lin;
    int woff;
    float badd = 0.f;
    if (r < 8) {
        x = groups + (b * 8 + r) * 64;
        outw = g_hgw + (b * 8 + r) * 64;
        lin = g_linG + b * 8 + r;
        woff = 0;
    } else if (r < 136) {
        int f = r - 8;
        x = cities + (b * 128 + f) * 64;
        outw = g_hfw + (b * 128 + f) * 64;
        lin = g_linF + b * 128 + f;
        woff = 64;
        badd = b1[e];
    } else {
        int t = r - 136;
        x = cities + (b * 128 + t) * 64;
        outw = g_htw + (b * 128 + t) * 64;
        lin = g_linT + b * 128 + t;
        woff = 128;
    }
    xv[e] = x[e];
    __syncthreads();

    const float* Wbase = W1 + woff * 64 + e;
    float acc = 0.f;
#pragma unroll
    for (int kb = 0; kb < 64; kb += 16) {
        float wv[16];
#pragma unroll
        for (int i = 0; i < 16; i++) wv[i] = Wbase[(kb + i) * 64];
#pragma unroll
        for (int i = 0; i < 16; i++) acc += xv[kb + i] * wv[i];
    }
    float h = acc + badd;
    float w = W2[e];
    outw[e] = h * fabsf(w);

    float p = warpReduceSum(h * w);
    if ((e & 31) == 0) sred2[e >> 5] = p;
    __syncthreads();
    if (e == 0) *lin = sred2[0] + sred2[1];
}

// ---------------------------------------------------------------------------
// K2 k_out: grid (128,4) x 128 (R7, with clamp-free row sums).
// ---------------------------------------------------------------------------
__global__ void __launch_bounds__(128) k_out(const float* __restrict__ W2,
                                             const float* __restrict__ b2) {
    pdl_trigger();
    int b = blockIdx.y, f = blockIdx.x, t = threadIdx.x;
    int w = t >> 5, lane = t & 31;
    __shared__ ull sh_gw[8 * 32];
    __shared__ unsigned sh_sgu[64];
    __shared__ float sh_linG[8];
    __shared__ float s_red[8][4];
    __shared__ float s_bc[8];
    __shared__ float s_m4[4];

    // producer-independent preamble
    if (t < 64) sh_sgu[t] = __float_as_uint(W2[t]) & 0x80000000u;
    float b2v = b2[0];

    pdl_wait();

    for (int idx = t; idx < 256; idx += 128) {
        int m = idx >> 5, ee2 = idx & 31;
        int e = 2 * ee2;
        float a0 = g_hgw[(b * 8 + m) * 64 + e] + g_hfw[(b * 128 + f) * 64 + e];
        float a1 = g_hgw[(b * 8 + m) * 64 + e + 1] + g_hfw[(b * 128 + f) * 64 + e + 1];
        sh_gw[m * 32 + ee2] = (ull)__float_as_uint(a0) | ((ull)__float_as_uint(a1) << 32);
    }
    if (t < 8) sh_linG[t] = g_linG[b * 8 + t];
    __syncthreads();

    union {
        float4 f4[16];
        ull u[32];
    } tw;
    const float4* src = (const float4*)(g_htw + (b * 128 + t) * 64);
#pragma unroll
    for (int i = 0; i < 16; i++) tw.f4[i] = src[i];

    ull accs[8];
#pragma unroll
    for (int m = 0; m < 8; m++) accs[m] = 0ull;
#pragma unroll
    for (int ee2 = 0; ee2 < 32; ee2++) {
        unsigned sl = sh_sgu[2 * ee2], sh2 = sh_sgu[2 * ee2 + 1];
        ull th = tw.u[ee2];
#pragma unroll
        for (int m = 0; m < 8; m++) mac2(accs[m], sh_gw[m * 32 + ee2], th, sl, sh2);
    }

    float linFT = g_linF[b * 128 + f] + g_linT[b * 128 + t];
    float vals[8];
#pragma unroll
    for (int m = 0; m < 8; m++) {
        float nl = __uint_as_float((unsigned)(accs[m] & 0xffffffffull)) +
                   __uint_as_float((unsigned)(accs[m] >> 32));
        vals[m] = 0.5f * (sh_linG[m] + linFT + nl) + b2v;
    }

    if (f == 0) {
#pragma unroll
        for (int m = 0; m < 8; m++) {
            float mm = warpReduceMax(vals[m]);
            if (lane == 0) s_red[m][w] = mm;
        }
        __syncthreads();
        if (t < 8) s_bc[t] = fmaxf(fmaxf(s_red[t][0], s_red[t][1]), fmaxf(s_red[t][2], s_red[t][3]));
        __syncthreads();
#pragma unroll
        for (int m = 0; m < 8; m++) {
            float ev = expf(vals[m] - s_bc[m]);
            g_buf[((b * 8 + m) * 128 + 0) * 128 + t] = ev;
            float s = warpReduceSum(ev);
            if (lane == 0) s_red[m][w] = s;
        }
        __syncthreads();
        if (t < 8)
            g_rowpart[(b * 8 + t) * 128 + 0] = s_red[t][0] + s_red[t][1] + s_red[t][2] + s_red[t][3];
    } else {
        float lm = vals[0];
#pragma unroll
        for (int m = 1; m < 8; m++) lm = fmaxf(lm, vals[m]);
        lm = warpReduceMax(lm);
        if (lane == 0) s_m4[w] = lm;
        __syncthreads();
        float mx = fmaxf(fmaxf(s_m4[0], s_m4[1]), fmaxf(s_m4[2], s_m4[3]));
#pragma unroll
        for (int m = 0; m < 8; m++) {
            float ev = expf(vals[m] - mx);
            g_buf[((b * 8 + m) * 128 + f) * 128 + t] = ev;
            float s = warpReduceSum(ev);
            if (lane == 0) s_red[m][w] = s;
        }
        __syncthreads();
        if (t < 8)
            g_rowpart[(b * 8 + t) * 128 + f] = s_red[t][0] + s_red[t][1] + s_red[t][2] + s_red[t][3];
    }
}

// ---------------------------------------------------------------------------
// K3 k_soft v5: same partition/sync as v3 (known-good), but EPS clamps removed
// (numerically vacuous after max-subtracted exp; all values positive and every
// normalization group contains an O(1) element) and the scale/reduce pipeline
// fully packed in f32x2. Thread state: V[m] = (v[m][y0], v[m][y1]) in one ull.
// ---------------------------------------------------------------------------
__global__ void __cluster_dims__(8, 1, 1) __launch_bounds__(1024, 1)
k_soft(float* __restrict__ out) {
    cg::cluster_group cl = cg::this_cluster();
    const int rk = (int)cl.block_rank();
    const int b = blockIdx.x >> 3;
    const int tid = threadIdx.x;
    const int x = tid >> 3;
    const int jq = tid & 7;
    const int w = tid >> 5;
    const int lane = tid & 31;
    const int yb = rk * 16;
    const bool x0 = (x == 0);
    const bool y0th = (rk == 0 && jq == 0);  // lo element is y==0

    __shared__ float s_dinv[128];
    __shared__ float s_d0inv[8];
    __shared__ float s_cdinv[16];   // [jq*2+j], 8B-aligned pairs
    __shared__ float s_c0inv[8];
    __shared__ float s_wpp[32][16];
    __shared__ float s_y0p[32][8];
    __shared__ float s_xs[2][128];
    __shared__ float s_x0[2][8];

    pdl_wait();

    // ---- load slab packed ----
    ull V[8];
#pragma unroll
    for (int m = 0; m < 8; m++) {
        const float2* p =
            (const float2*)(g_buf + ((size_t)((b * 8 + m) * 128 + x)) * 128 + yb + jq * 2);
        float2 t2 = *p;
        V[m] = pk2(t2.x, t2.y);
    }

    // ---- layer-0 even dens from g_rowpart ----
    if (tid < 128) {
        float d = 0.f;
#pragma unroll
        for (int m = 0; m < 8; m++) d += g_rowpart[(b * 8 + m) * 128 + tid];
        s_dinv[tid] = 1.0f / d;
    } else if (tid < 136) {
        s_d0inv[tid - 128] = 1.0f / g_rowpart[(b * 8 + (tid - 128)) * 128];
    }
    __syncthreads();

#pragma unroll 1
    for (int half = 0; half < 5; half++) {
        // ===== EVEN layer scale (packed) + odd-den partials =====
        {
            float rinv = s_dinv[x];
            ull acc2 = 0ull;
#pragma unroll
            for (int m = 0; m < 8; m++) {
                float dm = x0 ? s_d0inv[m] : rinv;
                V[m] = mul2(V[m], pk2(dm, dm));
                acc2 = add2(acc2, V[m]);
            }
            float sj0 = lo2(acc2), sj1 = hi2(acc2);
            sj0 += __shfl_xor_sync(0xffffffffu, sj0, 8);
            sj0 += __shfl_xor_sync(0xffffffffu, sj0, 16);
            sj1 += __shfl_xor_sync(0xffffffffu, sj1, 8);
            sj1 += __shfl_xor_sync(0xffffffffu, sj1, 16);
            if ((lane >> 3) == 0) {
                s_wpp[w][jq * 2 + 0] = sj0;
                s_wpp[w][jq * 2 + 1] = sj1;
            }
            if (rk == 0) {
#pragma unroll
                for (int m = 0; m < 8; m++) {
                    float t = lo2(V[m]);
                    t += __shfl_xor_sync(0xffffffffu, t, 8);
                    t += __shfl_xor_sync(0xffffffffu, t, 16);
                    if (lane == 0) s_y0p[w][m] = t;
                }
            }
        }
        __syncthreads();  // bar1
        if (tid < 16) {
            float d = 0.f;
#pragma unroll
            for (int ww = 0; ww < 32; ww++) d += s_wpp[ww][tid];
            s_cdinv[tid] = 1.0f / d;
        } else if (tid < 24 && rk == 0) {
            int m = tid - 16;
            float d = 0.f;
#pragma unroll
            for (int ww = 0; ww < 32; ww++) d += s_y0p[ww][m];
            s_c0inv[m] = 1.0f / d;
        }
        __syncthreads();  // bar2

        // ===== ODD layer scale (packed) =====
        ull rj2 = *(const ull*)&s_cdinv[jq * 2];
        if (half == 4) {
#pragma unroll
            for (int m = 0; m < 8; m++) {
                ull s = y0th ? pk2(lo2(V[m]) * s_c0inv[m], hi2(V[m]) * hi2(rj2))
                             : mul2(V[m], rj2);
                float2 o;
                o.x = lo2(s);
                o.y = hi2(s);
                *(float2*)(out + ((size_t)((b * 8 + m) * 128 + x)) * 128 + yb + jq * 2) = o;
            }
            break;
        }
        {
            ull acc2 = 0ull;
#pragma unroll
            for (int m = 0; m < 8; m++) {
                ull s = y0th ? pk2(lo2(V[m]) * s_c0inv[m], hi2(V[m]) * hi2(rj2))
                             : mul2(V[m], rj2);
                V[m] = s;
                acc2 = add2(acc2, s);
            }
            float rp = lo2(acc2) + hi2(acc2);
            rp += __shfl_xor_sync(0xffffffffu, rp, 1);
            rp += __shfl_xor_sync(0xffffffffu, rp, 2);
            rp += __shfl_xor_sync(0xffffffffu, rp, 4);
            int p = half & 1;
            if ((lane & 7) == 0) s_xs[p][x] = rp;
            if (w == 0) {
#pragma unroll
                for (int m = 0; m < 8; m++) {
                    float t = lo2(V[m]) + hi2(V[m]);
                    t += __shfl_xor_sync(0xffffffffu, t, 1);
                    t += __shfl_xor_sync(0xffffffffu, t, 2);
                    t += __shfl_xor_sync(0xffffffffu, t, 4);
                    if (lane == 0) s_x0[p][m] = t;
                }
            }
        }
        cl.sync();

        // ---- gather peers' sums -> next even dens ----
        {
            int p = half & 1;
            if (tid < 128) {
                float d = 0.f;
#pragma unroll
                for (int r = 0; r < 8; r++) {
                    const float* pp = cl.map_shared_rank((const float*)&s_xs[p][0], r);
                    d += pp[tid];
                }
                s_dinv[tid] = 1.0f / d;
            } else if (tid < 136) {
                int m = tid - 128;
                float d = 0.f;
#pragma unroll
                for (int r = 0; r < 8; r++) {
                    const float* pp = cl.map_shared_rank((const float*)&s_x0[p][0], r);
                    d += pp[m];
                }
                s_d0inv[m] = 1.0f / d;
            }
        }
        __syncthreads();  // bar3
    }

    cl.sync();  // keep SMEM alive until all peers finished DSMEM reads
}

// ---------------------------------------------------------------------------
// Launch: 3 kernels, PDL-chained.
// ---------------------------------------------------------------------------
extern "C" void kernel_launch(void* const* d_in, const int* in_sizes, int n_in,
                              void* d_out, int out_size) {
    const float* cities = (const float*)d_in[0];
    const float* groups = (const float*)d_in[1];
    const float* W1 = (const float*)d_in[2];
    const float* b1 = (const float*)d_in[3];
    const float* W2 = (const float*)d_in[4];
    const float* b2 = (const float*)d_in[5];
    float* out = (float*)d_out;

    k_proj<<<dim3(264, 4), 64>>>(cities, groups, W1, b1, W2);

    {
        cudaLaunchConfig_t cfg = {};
        cfg.gridDim = dim3(128, 4);
        cfg.blockDim = dim3(128);
        cfg.stream = 0;
        cudaLaunchAttribute at[1];
        at[0].id = cudaLaunchAttributeProgrammaticStreamSerialization;
        at[0].val.programmaticStreamSerializationAllowed = 1;
        cfg.attrs = at;
        cfg.numAttrs = 1;
        cudaLaunchKernelEx(&cfg, k_out, W2, b2);
    }

    {
        cudaLaunchConfig_t cfg = {};
        cfg.gridDim = dim3(32);
        cfg.blockDim = dim3(1024);
        cfg.stream = 0;
        cudaLaunchAttribute at[1];
        at[0].id = cudaLaunchAttributeProgrammaticStreamSerialization;
        at[0].val.programmaticStreamSerializationAllowed = 1;
        cfg.attrs = at;
        cfg.numAttrs = 1;
        cudaLaunchKernelEx(&cfg, k_soft, out);
    }
}